// round 4
// baseline (speedup 1.0000x reference)
#include <cuda_runtime.h>
#include <cuda_bf16.h>
#include <math.h>
#include <cstdint>

#define BATCH 16
#define NPART 256
#define DMODEL 128
#define NHEAD 8
#define HDIM 16
#define NTILES 16
#define NTRI 136

#define PI_F 3.14159265358979323846f
#define TWO_PI_F 6.28318530717958647692f
#define INV_TWO_PI_F 0.15915494309189533577f
#define EPS_F 1e-8f

// A rows stride 72 bf16 (144B) -> conflict-free ldmatrix-style LDS patterns
#define ASTR 72

// ---------------- scratch ----------------
__device__ float g_bias[BATCH * NHEAD * NPART * NPART]; // [b][h][j][i]
__device__ float g_q[BATCH * NPART * DMODEL];
__device__ float g_k[BATCH * NPART * DMODEL];
__device__ float g_v[BATCH * NPART * DMODEL];
__device__ float g_attn[BATCH * NPART * DMODEL];

// ---------------- pair kernel smem layout (bytes) ----------------
#define OFF_AH   0                       // 256 x 72 bf16 = 36864
#define OFF_AL   36864
#define OFF_WH2  73728                   // 64 x 72 bf16 = 9216 (W transposed: [n][k])
#define OFF_WL2  82944
#define OFF_WH3  92160
#define OFF_WL3  101376
#define OFF_W4H  110592                  // 8 x 72 bf16 = 1152
#define OFF_W4L  111744
#define OFF_W1   112896                  // 4x64 fp32 = 1024
#define OFF_B1   113920                  // 64 fp32
#define OFF_B2   114176
#define OFF_B3   114432
#define OFF_B4   114688                  // 8 fp32
#define OFF_PART 114720                  // 7 x 32 fp32 = 896
#define PAIR_SMEM 115712

__device__ __forceinline__ float gelu_f(float x) {
    float u = 0.7978845608028654f * (x + 0.044715f * x * x * x);
    return x / (1.0f + __expf(-2.0f * u));
}

// mma.sync m16n8k16 bf16 -> f32 accumulate (portable HMMA, sm_80+)
__device__ __forceinline__ void mma16816(float* d, const uint32_t* a, uint32_t b0, uint32_t b1) {
    asm volatile(
        "mma.sync.aligned.m16n8k16.row.col.f32.bf16.bf16.f32 "
        "{%0,%1,%2,%3}, {%4,%5,%6,%7}, {%8,%9}, {%0,%1,%2,%3};"
        : "+f"(d[0]), "+f"(d[1]), "+f"(d[2]), "+f"(d[3])
        : "r"(a[0]), "r"(a[1]), "r"(a[2]), "r"(a[3]), "r"(b0), "r"(b1));
}

__device__ __forceinline__ uint32_t lds32(const char* sm, int off, int row, int col) {
    return *(const uint32_t*)(sm + off + (row * ASTR + col) * 2);
}

// store bf16 hi/lo pair (2 adjacent cols) into A region
__device__ __forceinline__ void split_store_pair(char* sm, int row, int col, float x0, float x1) {
    __nv_bfloat16 h0 = __float2bfloat16_rn(x0);
    __nv_bfloat16 h1 = __float2bfloat16_rn(x1);
    __nv_bfloat162 hp = __halves2bfloat162(h0, h1);
    __nv_bfloat162 lp = __halves2bfloat162(__float2bfloat16_rn(x0 - __bfloat162float(h0)),
                                           __float2bfloat16_rn(x1 - __bfloat162float(h1)));
    uint32_t boff = (uint32_t)(row * ASTR + col) * 2;
    *(uint32_t*)(sm + OFF_AH + boff) = *(uint32_t*)&hp;
    *(uint32_t*)(sm + OFF_AL + boff) = *(uint32_t*)&lp;
}

// one 64->64 layer: C = gelu(A@W + b), A/W split bf16, result back into A (split)
__device__ __forceinline__ void mlp_mma_layer(char* sm, int offWH, int offWL,
                                              const float* __restrict__ Bv,
                                              int m0, int g, int t4) {
    float acc[2][8][4];
#pragma unroll
    for (int mt = 0; mt < 2; mt++)
#pragma unroll
        for (int nt = 0; nt < 8; nt++)
#pragma unroll
            for (int q = 0; q < 4; q++) acc[mt][nt][q] = 0.0f;

#pragma unroll
    for (int ks = 0; ks < 4; ks++) {
        const int k0 = ks * 16;
        const int kc = k0 + 2 * t4;
        uint32_t aH[2][4], aL[2][4];
#pragma unroll
        for (int mt = 0; mt < 2; mt++) {
            int r0 = m0 + mt * 16 + g;
            aH[mt][0] = lds32(sm, OFF_AH, r0, kc);
            aH[mt][1] = lds32(sm, OFF_AH, r0 + 8, kc);
            aH[mt][2] = lds32(sm, OFF_AH, r0, kc + 8);
            aH[mt][3] = lds32(sm, OFF_AH, r0 + 8, kc + 8);
            aL[mt][0] = lds32(sm, OFF_AL, r0, kc);
            aL[mt][1] = lds32(sm, OFF_AL, r0 + 8, kc);
            aL[mt][2] = lds32(sm, OFF_AL, r0, kc + 8);
            aL[mt][3] = lds32(sm, OFF_AL, r0 + 8, kc + 8);
        }
#pragma unroll
        for (int nt = 0; nt < 8; nt++) {
            int wr = nt * 8 + g;
            uint32_t bH0 = lds32(sm, offWH, wr, kc);
            uint32_t bH1 = lds32(sm, offWH, wr, kc + 8);
            uint32_t bL0 = lds32(sm, offWL, wr, kc);
            uint32_t bL1 = lds32(sm, offWL, wr, kc + 8);
#pragma unroll
            for (int mt = 0; mt < 2; mt++) {
                mma16816(acc[mt][nt], aH[mt], bH0, bH1);
                mma16816(acc[mt][nt], aH[mt], bL0, bL1);
                mma16816(acc[mt][nt], aL[mt], bH0, bH1);
            }
        }
    }
    __syncwarp();
#pragma unroll
    for (int mt = 0; mt < 2; mt++) {
#pragma unroll
        for (int nt = 0; nt < 8; nt++) {
            int n0 = nt * 8 + 2 * t4;
            int r0 = m0 + mt * 16 + g;
            float bv0 = Bv[n0], bv1 = Bv[n0 + 1];
            split_store_pair(sm, r0, n0, gelu_f(acc[mt][nt][0] + bv0), gelu_f(acc[mt][nt][1] + bv1));
            split_store_pair(sm, r0 + 8, n0, gelu_f(acc[mt][nt][2] + bv0), gelu_f(acc[mt][nt][3] + bv1));
        }
    }
    __syncwarp();
}

// ---------------- pair kernel ----------------
__global__ void __launch_bounds__(256, 1) pair_kernel(
    const float* __restrict__ xpf,
    const float* __restrict__ w0, const float* __restrict__ b0,
    const float* __restrict__ w1, const float* __restrict__ b1,
    const float* __restrict__ w2, const float* __restrict__ b2,
    const float* __restrict__ w3, const float* __restrict__ b3) {
    extern __shared__ char sm[];
    float* smf = (float*)sm;
    const int tid = threadIdx.x;
    const int wid = tid >> 5, lane = tid & 31;
    const int g = lane >> 2, t4 = lane & 3;
    const int m0 = wid * 32;

    // ---- stage weights (transposed [n][k], split hi/lo) ----
    for (int idx = tid; idx < 4096; idx += 256) {
        int n = idx >> 6, k = idx & 63;
        uint32_t boff = (uint32_t)(n * ASTR + k) * 2;
        {
            float w = w1[k * 64 + n];
            __nv_bfloat16 h = __float2bfloat16_rn(w);
            *(__nv_bfloat16*)(sm + OFF_WH2 + boff) = h;
            *(__nv_bfloat16*)(sm + OFF_WL2 + boff) = __float2bfloat16_rn(w - __bfloat162float(h));
        }
        {
            float w = w2[k * 64 + n];
            __nv_bfloat16 h = __float2bfloat16_rn(w);
            *(__nv_bfloat16*)(sm + OFF_WH3 + boff) = h;
            *(__nv_bfloat16*)(sm + OFF_WL3 + boff) = __float2bfloat16_rn(w - __bfloat162float(h));
        }
    }
    for (int idx = tid; idx < 512; idx += 256) {   // w3: (64,8) -> [h][k]
        int h = idx & 7, k = idx >> 3;
        float w = w3[k * 8 + h];
        __nv_bfloat16 hh = __float2bfloat16_rn(w);
        uint32_t boff = (uint32_t)(h * ASTR + k) * 2;
        *(__nv_bfloat16*)(sm + OFF_W4H + boff) = hh;
        *(__nv_bfloat16*)(sm + OFF_W4L + boff) = __float2bfloat16_rn(w - __bfloat162float(hh));
    }
    if (tid < 256) smf[OFF_W1 / 4 + tid] = w0[tid];
    if (tid < 64) {
        smf[OFF_B1 / 4 + tid] = b0[tid];
        smf[OFF_B2 / 4 + tid] = b1[tid];
        smf[OFF_B3 / 4 + tid] = b2[tid];
    }
    if (tid < 8) smf[OFF_B4 / 4 + tid] = b3[tid];

    // ---- block -> (b, upper-tri tile) ----
    const int b = blockIdx.x / NTRI;
    int rem = blockIdx.x % NTRI;
    int ti = 0;
    while (rem >= NTILES - ti) { rem -= NTILES - ti; ti++; }
    const int tj = ti + rem;
    const int i0 = ti * 16, j0 = tj * 16;

    float* sPt = smf + OFF_PART / 4;
    float* sRap = sPt + 32; float* sPhi = sRap + 32;
    float* sPx = sPhi + 32; float* sPy = sPx + 32; float* sPz = sPy + 32; float* sE = sPz + 32;
    if (tid < 32) {
        int l = tid & 15;
        int n = ((tid < 16) ? i0 : j0) + l;
        const float* base = xpf + b * 4 * NPART;
        float px = base[n], py = base[NPART + n], pz = base[2 * NPART + n], e = base[3 * NPART + n];
        sPx[tid] = px; sPy[tid] = py; sPz[tid] = pz; sE[tid] = e;
        sPt[tid] = sqrtf(fmaxf(px * px + py * py, EPS_F));
        sRap[tid] = 0.5f * log1pf(2.0f * pz / fmaxf(e - pz, 1e-20f));
        sPhi[tid] = atan2f(py, px);
    }
    __syncthreads();

    // ---- features + layer1 (4 -> 64), row = tid ----
    {
        int il = tid & 15, jl = tid >> 4;
        float pti = sPt[il], ptj = sPt[16 + jl];
        float drap = sRap[il] - sRap[16 + jl];
        float x = sPhi[il] - sPhi[16 + jl] + PI_F;
        float dphi = x - floorf(x * INV_TWO_PI_F) * TWO_PI_F - PI_F;
        float delta = sqrtf(drap * drap + dphi * dphi);
        float f2 = logf(fmaxf(delta, EPS_F));
        float ptmin = fminf(pti, ptj);
        float f0 = logf(fmaxf(ptmin * delta, EPS_F));
        float f1 = logf(fmaxf(ptmin / fmaxf(pti + ptj, EPS_F), EPS_F));
        float es = sE[il] + sE[16 + jl];
        float pxs = sPx[il] + sPx[16 + jl];
        float pys = sPy[il] + sPy[16 + jl];
        float pzs = sPz[il] + sPz[16 + jl];
        float f3 = logf(fmaxf(es * es - pxs * pxs - pys * pys - pzs * pzs, EPS_F));
        const float* W1 = smf + OFF_W1 / 4;
        const float* B1 = smf + OFF_B1 / 4;
#pragma unroll
        for (int n = 0; n < 64; n += 2) {
            float v0 = B1[n]     + f0 * W1[n]     + f1 * W1[64 + n]     + f2 * W1[128 + n]     + f3 * W1[192 + n];
            float v1 = B1[n + 1] + f0 * W1[n + 1] + f1 * W1[64 + n + 1] + f2 * W1[128 + n + 1] + f3 * W1[192 + n + 1];
            split_store_pair(sm, tid, n, gelu_f(v0), gelu_f(v1));
        }
    }
    __syncwarp();

    // ---- layers 2,3 via HMMA ----
    mlp_mma_layer(sm, OFF_WH2, OFF_WL2, smf + OFF_B2 / 4, m0, g, t4);
    mlp_mma_layer(sm, OFF_WH3, OFF_WL3, smf + OFF_B3 / 4, m0, g, t4);

    // ---- layer4 (64 -> 8) via HMMA, single n-tile ----
    float a4[2][4];
#pragma unroll
    for (int mt = 0; mt < 2; mt++)
#pragma unroll
        for (int q = 0; q < 4; q++) a4[mt][q] = 0.0f;
#pragma unroll
    for (int ks = 0; ks < 4; ks++) {
        const int kc = ks * 16 + 2 * t4;
        uint32_t bH0 = lds32(sm, OFF_W4H, g, kc);
        uint32_t bH1 = lds32(sm, OFF_W4H, g, kc + 8);
        uint32_t bL0 = lds32(sm, OFF_W4L, g, kc);
        uint32_t bL1 = lds32(sm, OFF_W4L, g, kc + 8);
#pragma unroll
        for (int mt = 0; mt < 2; mt++) {
            int r0 = m0 + mt * 16 + g;
            uint32_t aH[4], aL[4];
            aH[0] = lds32(sm, OFF_AH, r0, kc);
            aH[1] = lds32(sm, OFF_AH, r0 + 8, kc);
            aH[2] = lds32(sm, OFF_AH, r0, kc + 8);
            aH[3] = lds32(sm, OFF_AH, r0 + 8, kc + 8);
            aL[0] = lds32(sm, OFF_AL, r0, kc);
            aL[1] = lds32(sm, OFF_AL, r0 + 8, kc);
            aL[2] = lds32(sm, OFF_AL, r0, kc + 8);
            aL[3] = lds32(sm, OFF_AL, r0 + 8, kc + 8);
            mma16816(a4[mt], aH, bH0, bH1);
            mma16816(a4[mt], aH, bL0, bL1);
            mma16816(a4[mt], aL, bH0, bH1);
        }
    }

    // ---- scatter to g_bias ([b][h][j][i]; symmetric mirror) ----
    {
        const float* B4 = smf + OFF_B4 / 4;
        const int h0 = 2 * t4, h1 = h0 + 1;
        float bb0 = B4[h0], bb1 = B4[h1];
        size_t base = (size_t)b * NHEAD * NPART * NPART;
        const bool mir = (ti != tj);
#pragma unroll
        for (int mt = 0; mt < 2; mt++) {
#pragma unroll
            for (int rr = 0; rr < 2; rr++) {
                int p = m0 + mt * 16 + g + rr * 8;
                int i = i0 + (p & 15), j = j0 + (p >> 4);
                float o0 = a4[mt][rr * 2] + bb0;
                float o1 = a4[mt][rr * 2 + 1] + bb1;
                g_bias[base + (size_t)h0 * (NPART * NPART) + j * NPART + i] = o0;
                g_bias[base + (size_t)h1 * (NPART * NPART) + j * NPART + i] = o1;
                if (mir) {
                    g_bias[base + (size_t)h0 * (NPART * NPART) + i * NPART + j] = o0;
                    g_bias[base + (size_t)h1 * (NPART * NPART) + i * NPART + j] = o1;
                }
            }
        }
    }
}

// ---------------- projections with smem-staged weights ----------------
__device__ __forceinline__ void proj_body(const float* __restrict__ X,
                                          const float* __restrict__ W,
                                          const float* __restrict__ Bv,
                                          float* __restrict__ Out, int row0) {
    extern __shared__ float s[];
    float* sW = s;             // 128*128
    float* sX = s + 16384;     // 32*129
    const int tid = threadIdx.x;
    for (int idx = tid; idx < 16384; idx += 256) sW[idx] = W[idx];
    for (int idx = tid; idx < 4096; idx += 256)
        sX[(idx >> 7) * 129 + (idx & 127)] = X[row0 * 128 + idx];
    __syncthreads();
    const int tc = tid & 15, tr = tid >> 4;
    const int c0 = tc * 8, ra = tr * 2;
    float acc[2][8];
#pragma unroll
    for (int cc = 0; cc < 8; cc++) { float v = Bv[c0 + cc]; acc[0][cc] = v; acc[1][cc] = v; }
#pragma unroll 4
    for (int k = 0; k < 128; k++) {
        float x0 = sX[ra * 129 + k], x1 = sX[(ra + 1) * 129 + k];
        float4 w0 = *(const float4*)(sW + k * 128 + c0);
        float4 w1 = *(const float4*)(sW + k * 128 + c0 + 4);
        float fw[8] = {w0.x, w0.y, w0.z, w0.w, w1.x, w1.y, w1.z, w1.w};
#pragma unroll
        for (int cc = 0; cc < 8; cc++) {
            acc[0][cc] = fmaf(x0, fw[cc], acc[0][cc]);
            acc[1][cc] = fmaf(x1, fw[cc], acc[1][cc]);
        }
    }
#pragma unroll
    for (int r = 0; r < 2; r++) {
        int row = row0 + ra + r;
        *(float4*)(Out + row * 128 + c0)     = make_float4(acc[r][0], acc[r][1], acc[r][2], acc[r][3]);
        *(float4*)(Out + row * 128 + c0 + 4) = make_float4(acc[r][4], acc[r][5], acc[r][6], acc[r][7]);
    }
}

__global__ __launch_bounds__(256) void qkv_kernel(
    const float* __restrict__ X,
    const float* __restrict__ wq, const float* __restrict__ wk, const float* __restrict__ wv,
    const float* __restrict__ bq, const float* __restrict__ bk, const float* __restrict__ bv) {
    const int op = blockIdx.y;
    const float* W = (op == 0) ? wq : (op == 1) ? wk : wv;
    const float* Bv = (op == 0) ? bq : (op == 1) ? bk : bv;
    float* Out = (op == 0) ? g_q : (op == 1) ? g_k : g_v;
    proj_body(X, W, Bv, Out, blockIdx.x * 32);
}

__global__ __launch_bounds__(256) void outproj_kernel(
    const float* __restrict__ wo, const float* __restrict__ bo, float* __restrict__ out) {
    proj_body(g_attn, wo, bo, out, blockIdx.x * 32);
}

// ---------------- attention: one block per (b,h), bias chunked via smem -----------
__global__ __launch_bounds__(256) void attn_kernel() {
    extern __shared__ float s[];
    float* sK = s;             // 256*16
    float* sV = s + 4096;      // 256*16
    float* sB = s + 8192;      // 32*256
    const int tid = threadIdx.x;
    const int b = blockIdx.x >> 3, h = blockIdx.x & 7;

    {
        const float4* kp = (const float4*)(g_k + (b * NPART + tid) * DMODEL + h * HDIM);
        const float4* vp = (const float4*)(g_v + (b * NPART + tid) * DMODEL + h * HDIM);
        float4* kd = (float4*)(sK + tid * HDIM);
        float4* vd = (float4*)(sV + tid * HDIM);
#pragma unroll
        for (int d4 = 0; d4 < 4; d4++) { kd[d4] = kp[d4]; vd[d4] = vp[d4]; }
    }
    float q[16];
    {
        const float4* qp = (const float4*)(g_q + (b * NPART + tid) * DMODEL + h * HDIM);
#pragma unroll
        for (int d4 = 0; d4 < 4; d4++) {
            float4 v = qp[d4];
            q[d4 * 4] = v.x; q[d4 * 4 + 1] = v.y; q[d4 * 4 + 2] = v.z; q[d4 * 4 + 3] = v.w;
        }
    }

    float m = -1e30f, l = 0.0f, acc[16];
#pragma unroll
    for (int d = 0; d < 16; d++) acc[d] = 0.0f;
    const float* bias_base = g_bias + ((size_t)(b * NHEAD + h)) * (NPART * NPART);

    for (int j0 = 0; j0 < NPART; j0 += 32) {
        __syncthreads();
        for (int idx = tid; idx < 32 * 256; idx += 256)
            sB[idx] = bias_base[j0 * 256 + idx];
        __syncthreads();
#pragma unroll 2
        for (int jj = 0; jj < 32; jj++) {
            int j = j0 + jj;
            const float4* kj = (const float4*)(sK + j * HDIM);
            float4 k0 = kj[0], k1 = kj[1], k2 = kj[2], k3 = kj[3];
            float dot = q[0] * k0.x + q[1] * k0.y + q[2] * k0.z + q[3] * k0.w
                      + q[4] * k1.x + q[5] * k1.y + q[6] * k1.z + q[7] * k1.w
                      + q[8] * k2.x + q[9] * k2.y + q[10] * k2.z + q[11] * k2.w
                      + q[12] * k3.x + q[13] * k3.y + q[14] * k3.z + q[15] * k3.w;
            float sscore = 0.25f * dot + sB[jj * 256 + tid];
            float mn = fmaxf(m, sscore);
            float corr = __expf(m - mn);
            float p = __expf(sscore - mn);
            l = l * corr + p;
            m = mn;
            const float4* vj = (const float4*)(sV + j * HDIM);
            float4 v0 = vj[0], v1 = vj[1], v2 = vj[2], v3 = vj[3];
            float vv[16] = {v0.x, v0.y, v0.z, v0.w, v1.x, v1.y, v1.z, v1.w,
                            v2.x, v2.y, v2.z, v2.w, v3.x, v3.y, v3.z, v3.w};
#pragma unroll
            for (int d = 0; d < 16; d++) acc[d] = fmaf(acc[d], corr, p * vv[d]);
        }
    }
    float inv = 1.0f / l;
    float* op = g_attn + (b * NPART + tid) * DMODEL + h * HDIM;
#pragma unroll
    for (int d = 0; d < 16; d++) op[d] = acc[d] * inv;
}

extern "C" void kernel_launch(void* const* d_in, const int* in_sizes, int n_in,
                              void* d_out, int out_size) {
    const float* x_pf   = (const float*)d_in[0];
    const float* x_feat = (const float*)d_in[1];
    const float* pw0 = (const float*)d_in[2];
    const float* pb0 = (const float*)d_in[3];
    const float* pw1 = (const float*)d_in[4];
    const float* pb1 = (const float*)d_in[5];
    const float* pw2 = (const float*)d_in[6];
    const float* pb2 = (const float*)d_in[7];
    const float* pw3 = (const float*)d_in[8];
    const float* pb3 = (const float*)d_in[9];
    const float* wq = (const float*)d_in[10];
    const float* wk = (const float*)d_in[11];
    const float* wv = (const float*)d_in[12];
    const float* wo = (const float*)d_in[13];
    const float* bq = (const float*)d_in[14];
    const float* bk = (const float*)d_in[15];
    const float* bv = (const float*)d_in[16];
    const float* bo = (const float*)d_in[17];
    float* out = (float*)d_out;

    cudaFuncSetAttribute(pair_kernel, cudaFuncAttributeMaxDynamicSharedMemorySize, PAIR_SMEM);
    cudaFuncSetAttribute(qkv_kernel, cudaFuncAttributeMaxDynamicSharedMemorySize, 82048);
    cudaFuncSetAttribute(outproj_kernel, cudaFuncAttributeMaxDynamicSharedMemorySize, 82048);
    cudaFuncSetAttribute(attn_kernel, cudaFuncAttributeMaxDynamicSharedMemorySize, 65536);

    pair_kernel<<<BATCH * NTRI, 256, PAIR_SMEM>>>(x_pf, pw0, pb0, pw1, pb1, pw2, pb2, pw3, pb3);
    qkv_kernel<<<dim3((BATCH * NPART) / 32, 3), 256, 82048>>>(x_feat, wq, wk, wv, bq, bk, bv);
    attn_kernel<<<BATCH * NHEAD, 256, 65536>>>();
    outproj_kernel<<<(BATCH * NPART) / 32, 256, 82048>>>(wo, bo, out);
}

// round 5
// speedup vs baseline: 1.1580x; 1.1580x over previous
#include <cuda_runtime.h>
#include <cuda_fp16.h>
#include <math.h>
#include <cstdint>

#define BATCH 16
#define NPART 256
#define DMODEL 128
#define NHEAD 8
#define HDIM 16
#define NTILES 16
#define NTRI 136

#define PI_F 3.14159265358979323846f
#define TWO_PI_F 6.28318530717958647692f
#define INV_TWO_PI_F 0.15915494309189533577f
#define EPS_F 1e-8f

// A rows stride 72 fp16 (144B) -> conflict-free fragment LDS
#define ASTR 72

// ---------------- scratch ----------------
__device__ float g_bias[BATCH * NHEAD * NPART * NPART]; // [b][h][j][i]
__device__ float g_q[BATCH * NPART * DMODEL];
__device__ float g_k[BATCH * NPART * DMODEL];
__device__ float g_v[BATCH * NPART * DMODEL];
__device__ float g_attn[BATCH * NPART * DMODEL];

// ---------------- pair kernel smem layout (bytes) ----------------
#define OFF_AH   0                       // 256 x 72 fp16 = 36864
#define OFF_AL   36864
#define OFF_W2   73728                   // 64 x 72 fp16 = 9216 ([n][k])
#define OFF_W3   82944
#define OFF_W4H  92160                   // 8 x 72 fp16 = 1152
#define OFF_W4L  93312
#define OFF_W1   94464                   // 4x64 fp32 = 1024
#define OFF_B1   95488
#define OFF_B2   95744
#define OFF_B3   96000
#define OFF_B4   96256
#define OFF_PART 96288                   // 7 x 32 fp32 = 896
#define PAIR_SMEM 97280

__device__ __forceinline__ float gelu_f(float x) {
    float u = 0.7978845608028654f * (x + 0.044715f * x * x * x);
    return x / (1.0f + __expf(-2.0f * u));
}

// mma.sync m16n8k16 fp16 -> f32 accumulate (portable HMMA, sm_80+)
__device__ __forceinline__ void mma16816(float* d, const uint32_t* a, uint32_t b0, uint32_t b1) {
    asm volatile(
        "mma.sync.aligned.m16n8k16.row.col.f32.f16.f16.f32 "
        "{%0,%1,%2,%3}, {%4,%5,%6,%7}, {%8,%9}, {%0,%1,%2,%3};"
        : "+f"(d[0]), "+f"(d[1]), "+f"(d[2]), "+f"(d[3])
        : "r"(a[0]), "r"(a[1]), "r"(a[2]), "r"(a[3]), "r"(b0), "r"(b1));
}

__device__ __forceinline__ uint32_t lds32(const char* sm, int off, int row, int col) {
    return *(const uint32_t*)(sm + off + (row * ASTR + col) * 2);
}

// store fp16 hi/lo pair (2 adjacent cols) into A region
__device__ __forceinline__ void split_store_pair(char* sm, int row, int col, float x0, float x1) {
    __half h0 = __float2half_rn(x0);
    __half h1 = __float2half_rn(x1);
    __half2 hp = __halves2half2(h0, h1);
    __half2 lp = __halves2half2(__float2half_rn(x0 - __half2float(h0)),
                                __float2half_rn(x1 - __half2float(h1)));
    uint32_t boff = (uint32_t)(row * ASTR + col) * 2;
    *(uint32_t*)(sm + OFF_AH + boff) = *(uint32_t*)&hp;
    *(uint32_t*)(sm + OFF_AL + boff) = *(uint32_t*)&lp;
}

// one 64->64 layer: C = gelu(A@W + b); A split fp16 (2 terms), W single fp16
__device__ __forceinline__ void mlp_mma_layer(char* sm, int offW,
                                              const float* __restrict__ Bv,
                                              int m0, int g, int t4) {
    float acc[2][8][4];
#pragma unroll
    for (int mt = 0; mt < 2; mt++)
#pragma unroll
        for (int nt = 0; nt < 8; nt++)
#pragma unroll
            for (int q = 0; q < 4; q++) acc[mt][nt][q] = 0.0f;

#pragma unroll
    for (int ks = 0; ks < 4; ks++) {
        const int kc = ks * 16 + 2 * t4;
        uint32_t aH[2][4], aL[2][4];
#pragma unroll
        for (int mt = 0; mt < 2; mt++) {
            int r0 = m0 + mt * 16 + g;
            aH[mt][0] = lds32(sm, OFF_AH, r0, kc);
            aH[mt][1] = lds32(sm, OFF_AH, r0 + 8, kc);
            aH[mt][2] = lds32(sm, OFF_AH, r0, kc + 8);
            aH[mt][3] = lds32(sm, OFF_AH, r0 + 8, kc + 8);
            aL[mt][0] = lds32(sm, OFF_AL, r0, kc);
            aL[mt][1] = lds32(sm, OFF_AL, r0 + 8, kc);
            aL[mt][2] = lds32(sm, OFF_AL, r0, kc + 8);
            aL[mt][3] = lds32(sm, OFF_AL, r0 + 8, kc + 8);
        }
#pragma unroll
        for (int nt = 0; nt < 8; nt++) {
            int wr = nt * 8 + g;
            uint32_t b0 = lds32(sm, offW, wr, kc);
            uint32_t b1 = lds32(sm, offW, wr, kc + 8);
#pragma unroll
            for (int mt = 0; mt < 2; mt++) {
                mma16816(acc[mt][nt], aH[mt], b0, b1);
                mma16816(acc[mt][nt], aL[mt], b0, b1);
            }
        }
    }
    __syncwarp();
#pragma unroll
    for (int mt = 0; mt < 2; mt++) {
#pragma unroll
        for (int nt = 0; nt < 8; nt++) {
            int n0 = nt * 8 + 2 * t4;
            int r0 = m0 + mt * 16 + g;
            float bv0 = Bv[n0], bv1 = Bv[n0 + 1];
            split_store_pair(sm, r0, n0, gelu_f(acc[mt][nt][0] + bv0), gelu_f(acc[mt][nt][1] + bv1));
            split_store_pair(sm, r0 + 8, n0, gelu_f(acc[mt][nt][2] + bv0), gelu_f(acc[mt][nt][3] + bv1));
        }
    }
    __syncwarp();
}

// ---------------- pair kernel ----------------
__global__ void __launch_bounds__(256) pair_kernel(
    const float* __restrict__ xpf,
    const float* __restrict__ w0, const float* __restrict__ b0,
    const float* __restrict__ w1, const float* __restrict__ b1,
    const float* __restrict__ w2, const float* __restrict__ b2,
    const float* __restrict__ w3, const float* __restrict__ b3) {
    extern __shared__ char sm[];
    float* smf = (float*)sm;
    const int tid = threadIdx.x;
    const int wid = tid >> 5, lane = tid & 31;
    const int g = lane >> 2, t4 = lane & 3;
    const int m0 = wid * 32;

    // ---- stage weights: coalesced prefetch, then transpose-store [n][k] fp16 ----
    {
        float v1[16], v2[16];
#pragma unroll
        for (int t = 0; t < 16; t++) { v1[t] = w1[tid + 256 * t]; v2[t] = w2[tid + 256 * t]; }
#pragma unroll
        for (int t = 0; t < 16; t++) {
            int idx = tid + 256 * t;
            int k = idx >> 6, n = idx & 63;
            uint32_t boff = (uint32_t)(n * ASTR + k) * 2;
            *(__half*)(sm + OFF_W2 + boff) = __float2half_rn(v1[t]);
            *(__half*)(sm + OFF_W3 + boff) = __float2half_rn(v2[t]);
        }
        float v4[2];
#pragma unroll
        for (int t = 0; t < 2; t++) v4[t] = w3[tid + 256 * t];
#pragma unroll
        for (int t = 0; t < 2; t++) {
            int idx = tid + 256 * t;
            int k = idx >> 3, h = idx & 7;
            __half hh = __float2half_rn(v4[t]);
            uint32_t boff = (uint32_t)(h * ASTR + k) * 2;
            *(__half*)(sm + OFF_W4H + boff) = hh;
            *(__half*)(sm + OFF_W4L + boff) = __float2half_rn(v4[t] - __half2float(hh));
        }
    }
    if (tid < 256) smf[OFF_W1 / 4 + tid] = w0[tid];
    if (tid < 64) {
        smf[OFF_B1 / 4 + tid] = b0[tid];
        smf[OFF_B2 / 4 + tid] = b1[tid];
        smf[OFF_B3 / 4 + tid] = b2[tid];
    }
    if (tid < 8) smf[OFF_B4 / 4 + tid] = b3[tid];

    // ---- block -> (b, upper-tri tile) ----
    const int b = blockIdx.x / NTRI;
    int rem = blockIdx.x % NTRI;
    int ti = 0;
    while (rem >= NTILES - ti) { rem -= NTILES - ti; ti++; }
    const int tj = ti + rem;
    const int i0 = ti * 16, j0 = tj * 16;

    float* sPt = smf + OFF_PART / 4;
    float* sRap = sPt + 32; float* sPhi = sRap + 32;
    float* sPx = sPhi + 32; float* sPy = sPx + 32; float* sPz = sPy + 32; float* sE = sPz + 32;
    if (tid < 32) {
        int l = tid & 15;
        int n = ((tid < 16) ? i0 : j0) + l;
        const float* base = xpf + b * 4 * NPART;
        float px = base[n], py = base[NPART + n], pz = base[2 * NPART + n], e = base[3 * NPART + n];
        sPx[tid] = px; sPy[tid] = py; sPz[tid] = pz; sE[tid] = e;
        sPt[tid] = sqrtf(fmaxf(px * px + py * py, EPS_F));
        sRap[tid] = 0.5f * log1pf(2.0f * pz / fmaxf(e - pz, 1e-20f));
        sPhi[tid] = atan2f(py, px);
    }
    __syncthreads();

    // ---- features + layer1 (4 -> 64), row = tid ----
    {
        int il = tid & 15, jl = tid >> 4;
        float pti = sPt[il], ptj = sPt[16 + jl];
        float drap = sRap[il] - sRap[16 + jl];
        float x = sPhi[il] - sPhi[16 + jl] + PI_F;
        float dphi = x - floorf(x * INV_TWO_PI_F) * TWO_PI_F - PI_F;
        float delta = sqrtf(drap * drap + dphi * dphi);
        float f2 = logf(fmaxf(delta, EPS_F));
        float ptmin = fminf(pti, ptj);
        float f0 = logf(fmaxf(ptmin * delta, EPS_F));
        float f1 = logf(fmaxf(ptmin / fmaxf(pti + ptj, EPS_F), EPS_F));
        float es = sE[il] + sE[16 + jl];
        float pxs = sPx[il] + sPx[16 + jl];
        float pys = sPy[il] + sPy[16 + jl];
        float pzs = sPz[il] + sPz[16 + jl];
        float f3 = logf(fmaxf(es * es - pxs * pxs - pys * pys - pzs * pzs, EPS_F));
        const float* W1 = smf + OFF_W1 / 4;
        const float* B1 = smf + OFF_B1 / 4;
#pragma unroll
        for (int n = 0; n < 64; n += 2) {
            float v0 = B1[n]     + f0 * W1[n]     + f1 * W1[64 + n]     + f2 * W1[128 + n]     + f3 * W1[192 + n];
            float v1 = B1[n + 1] + f0 * W1[n + 1] + f1 * W1[64 + n + 1] + f2 * W1[128 + n + 1] + f3 * W1[192 + n + 1];
            split_store_pair(sm, tid, n, gelu_f(v0), gelu_f(v1));
        }
    }
    __syncwarp();

    // ---- layers 2,3 via HMMA (2-term) ----
    mlp_mma_layer(sm, OFF_W2, smf + OFF_B2 / 4, m0, g, t4);
    mlp_mma_layer(sm, OFF_W3, smf + OFF_B3 / 4, m0, g, t4);

    // ---- layer4 (64 -> 8) via HMMA, 3-term (exact-ish into bias) ----
    float a4[2][4];
#pragma unroll
    for (int mt = 0; mt < 2; mt++)
#pragma unroll
        for (int q = 0; q < 4; q++) a4[mt][q] = 0.0f;
#pragma unroll
    for (int ks = 0; ks < 4; ks++) {
        const int kc = ks * 16 + 2 * t4;
        uint32_t bH0 = lds32(sm, OFF_W4H, g, kc);
        uint32_t bH1 = lds32(sm, OFF_W4H, g, kc + 8);
        uint32_t bL0 = lds32(sm, OFF_W4L, g, kc);
        uint32_t bL1 = lds32(sm, OFF_W4L, g, kc + 8);
#pragma unroll
        for (int mt = 0; mt < 2; mt++) {
            int r0 = m0 + mt * 16 + g;
            uint32_t aH[4], aL[4];
            aH[0] = lds32(sm, OFF_AH, r0, kc);
            aH[1] = lds32(sm, OFF_AH, r0 + 8, kc);
            aH[2] = lds32(sm, OFF_AH, r0, kc + 8);
            aH[3] = lds32(sm, OFF_AH, r0 + 8, kc + 8);
            aL[0] = lds32(sm, OFF_AL, r0, kc);
            aL[1] = lds32(sm, OFF_AL, r0 + 8, kc);
            aL[2] = lds32(sm, OFF_AL, r0, kc + 8);
            aL[3] = lds32(sm, OFF_AL, r0 + 8, kc + 8);
            mma16816(a4[mt], aH, bH0, bH1);
            mma16816(a4[mt], aH, bL0, bL1);
            mma16816(a4[mt], aL, bH0, bH1);
        }
    }

    // ---- scatter to g_bias ([b][h][j][i]; symmetric mirror) ----
    {
        const float* B4 = smf + OFF_B4 / 4;
        const int h0 = 2 * t4, h1 = h0 + 1;
        float bb0 = B4[h0], bb1 = B4[h1];
        size_t base = (size_t)b * NHEAD * NPART * NPART;
        const bool mir = (ti != tj);
#pragma unroll
        for (int mt = 0; mt < 2; mt++) {
#pragma unroll
            for (int rr = 0; rr < 2; rr++) {
                int p = m0 + mt * 16 + g + rr * 8;
                int i = i0 + (p & 15), j = j0 + (p >> 4);
                float o0 = a4[mt][rr * 2] + bb0;
                float o1 = a4[mt][rr * 2 + 1] + bb1;
                g_bias[base + (size_t)h0 * (NPART * NPART) + j * NPART + i] = o0;
                g_bias[base + (size_t)h1 * (NPART * NPART) + j * NPART + i] = o1;
                if (mir) {
                    g_bias[base + (size_t)h0 * (NPART * NPART) + i * NPART + j] = o0;
                    g_bias[base + (size_t)h1 * (NPART * NPART) + i * NPART + j] = o1;
                }
            }
        }
    }
}

// ---------------- projections: prefetched smem-staged weights ----------------
#define SX_STR 132
__device__ __forceinline__ void proj_body(const float* __restrict__ X,
                                          const float* __restrict__ W,
                                          const float* __restrict__ Bv,
                                          float* __restrict__ Out, int row0) {
    extern __shared__ float s[];
    float* sW = s;                 // 128*128
    float* sX = s + 16384;         // 32*SX_STR
    const int tid = threadIdx.x;
    {
        const float4* Wp = (const float4*)W;
        float4 wv[16];
#pragma unroll
        for (int t = 0; t < 16; t++) wv[t] = Wp[tid + 256 * t];
#pragma unroll
        for (int t = 0; t < 16; t++) *(float4*)(sW + (tid + 256 * t) * 4) = wv[t];
        const float4* Xp = (const float4*)(X + row0 * 128);
        float4 xv[4];
#pragma unroll
        for (int t = 0; t < 4; t++) xv[t] = Xp[tid + 256 * t];
#pragma unroll
        for (int t = 0; t < 4; t++) {
            int f = tid + 256 * t;
            int row = f >> 5, c = f & 31;
            *(float4*)(sX + row * SX_STR + c * 4) = xv[t];
        }
    }
    __syncthreads();
    const int tc = tid & 15, tr = tid >> 4;
    const int c0 = tc * 8, ra = tr * 2;
    float acc[2][8];
#pragma unroll
    for (int cc = 0; cc < 8; cc++) { float v = Bv[c0 + cc]; acc[0][cc] = v; acc[1][cc] = v; }
#pragma unroll 4
    for (int k = 0; k < 128; k++) {
        float x0 = sX[ra * SX_STR + k], x1 = sX[(ra + 1) * SX_STR + k];
        float4 w0 = *(const float4*)(sW + k * 128 + c0);
        float4 w1 = *(const float4*)(sW + k * 128 + c0 + 4);
        float fw[8] = {w0.x, w0.y, w0.z, w0.w, w1.x, w1.y, w1.z, w1.w};
#pragma unroll
        for (int cc = 0; cc < 8; cc++) {
            acc[0][cc] = fmaf(x0, fw[cc], acc[0][cc]);
            acc[1][cc] = fmaf(x1, fw[cc], acc[1][cc]);
        }
    }
#pragma unroll
    for (int r = 0; r < 2; r++) {
        int row = row0 + ra + r;
        *(float4*)(Out + row * 128 + c0)     = make_float4(acc[r][0], acc[r][1], acc[r][2], acc[r][3]);
        *(float4*)(Out + row * 128 + c0 + 4) = make_float4(acc[r][4], acc[r][5], acc[r][6], acc[r][7]);
    }
}

#define PROJ_SMEM ((16384 + 32 * SX_STR) * 4)

__global__ __launch_bounds__(256) void qkv_kernel(
    const float* __restrict__ X,
    const float* __restrict__ wq, const float* __restrict__ wk, const float* __restrict__ wv,
    const float* __restrict__ bq, const float* __restrict__ bk, const float* __restrict__ bv) {
    const int op = blockIdx.y;
    const float* W = (op == 0) ? wq : (op == 1) ? wk : wv;
    const float* Bv = (op == 0) ? bq : (op == 1) ? bk : bv;
    float* Out = (op == 0) ? g_q : (op == 1) ? g_k : g_v;
    proj_body(X, W, Bv, Out, blockIdx.x * 32);
}

__global__ __launch_bounds__(256) void outproj_kernel(
    const float* __restrict__ wo, const float* __restrict__ bo, float* __restrict__ out) {
    proj_body(g_attn, wo, bo, out, blockIdx.x * 32);
}

// ---------------- attention: block = (b, h, i-half); 128 threads -----------------
__global__ __launch_bounds__(128) void attn_kernel() {
    extern __shared__ float s[];
    float* sK = s;             // 256*16
    float* sV = s + 4096;      // 256*16
    float* sB = s + 8192;      // 32*128
    const int tid = threadIdx.x;
    const int b = blockIdx.x, h = blockIdx.y, ihalf = blockIdx.z;
    const int i = ihalf * 128 + tid;

    {
        const float4* kg = (const float4*)g_k;
        const float4* vg = (const float4*)g_v;
        float4 kv[8], vv[8];
#pragma unroll
        for (int t = 0; t < 8; t++) {
            int f = tid + 128 * t;          // 1024 float4 total
            int row = f >> 2, d4 = f & 3;
            int src = (b * NPART + row) * (DMODEL / 4) + h * 4 + d4;
            kv[t] = kg[src];
            vv[t] = vg[src];
        }
#pragma unroll
        for (int t = 0; t < 8; t++) {
            int f = tid + 128 * t;
            ((float4*)sK)[f] = kv[t];
            ((float4*)sV)[f] = vv[t];
        }
    }
    float q[16];
    {
        const float4* qp = (const float4*)(g_q + (b * NPART + i) * DMODEL + h * HDIM);
#pragma unroll
        for (int d4 = 0; d4 < 4; d4++) {
            float4 v = qp[d4];
            q[d4 * 4] = v.x; q[d4 * 4 + 1] = v.y; q[d4 * 4 + 2] = v.z; q[d4 * 4 + 3] = v.w;
        }
    }

    float m = -1e30f, l = 0.0f, acc[16];
#pragma unroll
    for (int d = 0; d < 16; d++) acc[d] = 0.0f;
    const float* bias_base = g_bias + ((size_t)(b * NHEAD + h)) * (NPART * NPART) + ihalf * 128;

    for (int j0 = 0; j0 < NPART; j0 += 32) {
        __syncthreads();
        {
            float4 bv[8];
#pragma unroll
            for (int t = 0; t < 8; t++) {
                int f = tid + 128 * t;      // 1024 float4 = 32 rows x 128 floats
                int j = f >> 5, c = f & 31;
                bv[t] = *(const float4*)(bias_base + (j0 + j) * NPART + c * 4);
            }
#pragma unroll
            for (int t = 0; t < 8; t++) ((float4*)sB)[tid + 128 * t] = bv[t];
        }
        __syncthreads();
#pragma unroll 2
        for (int jj = 0; jj < 32; jj++) {
            int j = j0 + jj;
            const float4* kj = (const float4*)(sK + j * HDIM);
            float4 k0 = kj[0], k1 = kj[1], k2 = kj[2], k3 = kj[3];
            float dot = q[0] * k0.x + q[1] * k0.y + q[2] * k0.z + q[3] * k0.w
                      + q[4] * k1.x + q[5] * k1.y + q[6] * k1.z + q[7] * k1.w
                      + q[8] * k2.x + q[9] * k2.y + q[10] * k2.z + q[11] * k2.w
                      + q[12] * k3.x + q[13] * k3.y + q[14] * k3.z + q[15] * k3.w;
            float sscore = 0.25f * dot + sB[jj * 128 + tid];
            float mn = fmaxf(m, sscore);
            float corr = __expf(m - mn);
            float p = __expf(sscore - mn);
            l = l * corr + p;
            m = mn;
            const float4* vj = (const float4*)(sV + j * HDIM);
            float4 v0 = vj[0], v1 = vj[1], v2 = vj[2], v3 = vj[3];
            float vv[16] = {v0.x, v0.y, v0.z, v0.w, v1.x, v1.y, v1.z, v1.w,
                            v2.x, v2.y, v2.z, v2.w, v3.x, v3.y, v3.z, v3.w};
#pragma unroll
            for (int d = 0; d < 16; d++) acc[d] = fmaf(acc[d], corr, p * vv[d]);
        }
    }
    float inv = 1.0f / l;
    float* op = g_attn + (b * NPART + i) * DMODEL + h * HDIM;
#pragma unroll
    for (int d = 0; d < 16; d++) op[d] = acc[d] * inv;
}

#define ATTN_SMEM ((8192 + 32 * 128) * 4)

extern "C" void kernel_launch(void* const* d_in, const int* in_sizes, int n_in,
                              void* d_out, int out_size) {
    const float* x_pf   = (const float*)d_in[0];
    const float* x_feat = (const float*)d_in[1];
    const float* pw0 = (const float*)d_in[2];
    const float* pb0 = (const float*)d_in[3];
    const float* pw1 = (const float*)d_in[4];
    const float* pb1 = (const float*)d_in[5];
    const float* pw2 = (const float*)d_in[6];
    const float* pb2 = (const float*)d_in[7];
    const float* pw3 = (const float*)d_in[8];
    const float* pb3 = (const float*)d_in[9];
    const float* wq = (const float*)d_in[10];
    const float* wk = (const float*)d_in[11];
    const float* wv = (const float*)d_in[12];
    const float* wo = (const float*)d_in[13];
    const float* bq = (const float*)d_in[14];
    const float* bk = (const float*)d_in[15];
    const float* bv = (const float*)d_in[16];
    const float* bo = (const float*)d_in[17];
    float* out = (float*)d_out;

    cudaFuncSetAttribute(pair_kernel, cudaFuncAttributeMaxDynamicSharedMemorySize, PAIR_SMEM);
    cudaFuncSetAttribute(qkv_kernel, cudaFuncAttributeMaxDynamicSharedMemorySize, PROJ_SMEM);
    cudaFuncSetAttribute(outproj_kernel, cudaFuncAttributeMaxDynamicSharedMemorySize, PROJ_SMEM);
    cudaFuncSetAttribute(attn_kernel, cudaFuncAttributeMaxDynamicSharedMemorySize, ATTN_SMEM);

    pair_kernel<<<BATCH * NTRI, 256, PAIR_SMEM>>>(x_pf, pw0, pb0, pw1, pb1, pw2, pb2, pw3, pb3);
    qkv_kernel<<<dim3((BATCH * NPART) / 32, 3), 256, PROJ_SMEM>>>(x_feat, wq, wk, wv, bq, bk, bv);
    attn_kernel<<<dim3(BATCH, NHEAD, 2), 128, ATTN_SMEM>>>();
    outproj_kernel<<<(BATCH * NPART) / 32, 256, PROJ_SMEM>>>(wo, bo, out);
}